// round 10
// baseline (speedup 1.0000x reference)
#include <cuda_runtime.h>
#include <cuda_fp16.h>
#include <math.h>
#include <stdint.h>

#define DINLINE __device__ __forceinline__

// Problem constants: B=16, C=256, H=W=64, K=7, C/4=64, C*K*K=12544

// ---- scratch (static device allocations: allowed) ----
__device__ __align__(128) float g_pooled[16 * 256];            // [B, C]
__device__ __align__(128) float g_h[16 * 64];                  // [B, C/4]
__device__ __align__(128) float g_fused[16 * 256 * 49];        // [B, C, 49]
__device__ __align__(128) __half g_bh[16u*256u*64u*64u];       // dw out, fp16 (32 MB)
__device__ __align__(128) __half g_pwh[256 * 256];             // fp16 pw weights

// ===========================================================================
// PTX helpers (all legal on plain sm_100 target)
// ===========================================================================
DINLINE uint32_t smem_u32(const void* p) {
    uint32_t a;
    asm("{ .reg .u64 t; cvta.to.shared.u64 t, %1; cvt.u32.u64 %0, t; }" : "=r"(a) : "l"(p));
    return a;
}
DINLINE void ldsm_x4(uint32_t* r, uint32_t addr) {
    asm volatile("ldmatrix.sync.aligned.m8n8.x4.shared.b16 {%0,%1,%2,%3}, [%4];"
                 : "=r"(r[0]), "=r"(r[1]), "=r"(r[2]), "=r"(r[3]) : "r"(addr));
}
DINLINE void ldsm_x4_t(uint32_t* r, uint32_t addr) {
    asm volatile("ldmatrix.sync.aligned.m8n8.x4.trans.shared.b16 {%0,%1,%2,%3}, [%4];"
                 : "=r"(r[0]), "=r"(r[1]), "=r"(r[2]), "=r"(r[3]) : "r"(addr));
}
DINLINE void mma_f16(float* d, const uint32_t* a, const uint32_t* b) {
    asm volatile(
        "mma.sync.aligned.m16n8k16.row.col.f32.f16.f16.f32 "
        "{%0,%1,%2,%3}, {%4,%5,%6,%7}, {%8,%9}, {%0,%1,%2,%3};"
        : "+f"(d[0]), "+f"(d[1]), "+f"(d[2]), "+f"(d[3])
        : "r"(a[0]), "r"(a[1]), "r"(a[2]), "r"(a[3]), "r"(b[0]), "r"(b[1]));
}
DINLINE void cp16(uint32_t dst, const void* src) {
    asm volatile("cp.async.cg.shared.global [%0], [%1], 16;"
                 :: "r"(dst), "l"(__cvta_generic_to_global(src)));
}
DINLINE void cp_commit() { asm volatile("cp.async.commit_group;" ::: "memory"); }
DINLINE void cp_wait0()  { asm volatile("cp.async.wait_group 0;" ::: "memory"); }
DINLINE void cp_wait1()  { asm volatile("cp.async.wait_group 1;" ::: "memory"); }

// packed f32x2 ops (PTX ISA 8.6, sm_100+)
DINLINE uint64_t pack2(float lo, float hi) {
    uint64_t r;
    asm("mov.b64 %0, {%1, %2};" : "=l"(r) : "f"(lo), "f"(hi));
    return r;
}
DINLINE void unpack2(float& lo, float& hi, uint64_t v) {
    asm("mov.b64 {%0, %1}, %2;" : "=f"(lo), "=f"(hi) : "l"(v));
}
DINLINE void fma2(uint64_t& d, uint64_t a, uint64_t b) {
    asm("fma.rn.f32x2 %0, %1, %2, %0;" : "+l"(d) : "l"(a), "l"(b));
}

// ---------------------------------------------------------------------------
// Kernel 0: pw weights -> fp16
// ---------------------------------------------------------------------------
__global__ void pw_split(const float* __restrict__ pw) {
    int i = blockIdx.x * 256 + threadIdx.x;   // 65536 elems
    g_pwh[i] = __float2half_rn(pw[i]);
}

// ---------------------------------------------------------------------------
// Kernel 1: global average pool
// ---------------------------------------------------------------------------
__global__ void pool_kernel(const float* __restrict__ x) {
    int bc = blockIdx.x;
    const float4* xp = (const float4*)(x + (size_t)bc * 4096);
    float s = 0.f;
    #pragma unroll 4
    for (int i = threadIdx.x; i < 1024; i += 256) {
        float4 v = xp[i];
        s += (v.x + v.y) + (v.z + v.w);
    }
    __shared__ float red[256];
    red[threadIdx.x] = s;
    __syncthreads();
    for (int off = 128; off > 0; off >>= 1) {
        if (threadIdx.x < off) red[threadIdx.x] += red[threadIdx.x + off];
        __syncthreads();
    }
    if (threadIdx.x == 0) g_pooled[bc] = red[0] * (1.f / 4096.f);
}

// ---------------------------------------------------------------------------
// Kernel 2: h = gelu(pooled @ w1^T + b1)
// ---------------------------------------------------------------------------
__global__ void mlp1_kernel(const float* __restrict__ w1, const float* __restrict__ b1) {
    int b = blockIdx.x;
    int j = threadIdx.x;   // 0..63
    __shared__ float p[256];
    for (int i = threadIdx.x; i < 256; i += 64) p[i] = g_pooled[b * 256 + i];
    __syncthreads();
    float s = b1[j];
    const float* wr = w1 + (size_t)j * 256;
    #pragma unroll 8
    for (int c = 0; c < 256; c++) s += p[c] * wr[c];
    g_h[b * 64 + j] = 0.5f * s * (1.0f + erff(s * 0.70710678118654752f));
}

// ---------------------------------------------------------------------------
// Kernel 3: fused[b,wi] = dw[wi] + b2[wi] + sum_j h[b,j]*w2[wi,j]
// grid (98 wi-tiles, 2 b-groups); thread: 1 wi x 4 b.
// ---------------------------------------------------------------------------
__global__ void __launch_bounds__(256) fuse_kernel(const float* __restrict__ dw,
                                                   const float* __restrict__ w2,
                                                   const float* __restrict__ b2) {
    __shared__ float hs[8 * 64];
    __shared__ float w2s[128 * 68];
    int tid = threadIdx.x;
    int wi0 = blockIdx.x * 128;
    int b0 = blockIdx.y * 8;               // 8 batches per block

    if (tid < 128) *(float4*)(hs + tid * 4) = *(const float4*)(g_h + b0 * 64 + tid * 4);
    #pragma unroll
    for (int i = 0; i < 8; i++) {
        int lin = tid + i * 256;
        int r = lin >> 4, j4 = lin & 15;
        float4 v = *(const float4*)(w2 + (size_t)(wi0 + r) * 64 + j4 * 4);
        *(float4*)(w2s + r * 68 + j4 * 4) = v;
    }
    __syncthreads();

    int wiL = tid & 127;
    int bg = (tid >> 7) * 4;               // 0 or 4 within group
    int wi = wi0 + wiL;
    float base = dw[wi] + b2[wi];
    float acc[4];
    #pragma unroll
    for (int bb = 0; bb < 4; bb++) acc[bb] = base;

    const float* wr = w2s + wiL * 68;
    #pragma unroll
    for (int j4 = 0; j4 < 16; j4++) {
        float4 w = *(const float4*)(wr + j4 * 4);
        #pragma unroll
        for (int bb = 0; bb < 4; bb++) {
            float4 h = *(const float4*)(hs + (bg + bb) * 64 + j4 * 4);
            acc[bb] += w.x * h.x + w.y * h.y + w.z * h.z + w.w * h.w;
        }
    }
    #pragma unroll
    for (int bb = 0; bb < 4; bb++)
        g_fused[(size_t)(b0 + bg + bb) * 12544 + wi] = acc[bb];
}

// ---------------------------------------------------------------------------
// Kernel 4: per-sample depthwise 7x7 conv, pad=3, packed f32x2 math.
// Block = 32-row tile; thread = 2 rows x 4 cols (8 outputs).
// Weights pre-broadcast (w,w) in smem, loaded once per (ky,kx) with a
// 2-row alternating register buffer.  Output stored fp16 packed.
// ---------------------------------------------------------------------------
__global__ void __launch_bounds__(256, 2) dw_kernel(const float* __restrict__ x) {
    int bc = blockIdx.y;
    int rowBase = blockIdx.x * 32;
    const float* xp = x + (size_t)bc * 4096;

    __shared__ __align__(16) float s[38 * 70];
    __shared__ __align__(8) float2 wsh2[49];

    if (threadIdx.x < 49) {
        float wv = g_fused[bc * 49 + threadIdx.x];
        wsh2[threadIdx.x] = make_float2(wv, wv);
    }
    for (int i = threadIdx.x; i < 38 * 70; i += 256) {
        int r = i / 70, cc = i - r * 70;
        int gr = rowBase + r - 3, gc = cc - 3;
        s[i] = (gr >= 0 && gr < 64 && gc >= 0 && gc < 64) ? xp[gr * 64 + gc] : 0.f;
    }
    __syncthreads();

    const int tc = threadIdx.x & 15;
    const int c0 = tc * 4;                    // output cols c0..c0+3
    const int lr0 = (threadIdx.x >> 4) * 2;   // local output rows lr0, lr0+1

    uint64_t acc0a = 0, acc0b = 0, acc1a = 0, acc1b = 0;   // f32x2 zeros
    uint64_t wb[2][7];
    #pragma unroll
    for (int kx = 0; kx < 7; kx++) { wb[0][kx] = 0; wb[1][kx] = 0; }

    #pragma unroll
    for (int r = 0; r < 8; r++) {             // smem rows lr0+r
        // row values v[0..9] and all shifted pairs p[j]=(v[j],v[j+1])
        float v[10];
        const float* row = s + (lr0 + r) * 70 + c0;
        #pragma unroll
        for (int q = 0; q < 5; q++) *(float2*)&v[q * 2] = *(const float2*)(row + q * 2);
        uint64_t p[9];
        #pragma unroll
        for (int j = 0; j < 9; j++) p[j] = pack2(v[j], v[j + 1]);

        // load weight row ky=r into alternating buffer (broadcast LDS.64)
        if (r < 7) {
            #pragma unroll
            for (int kx = 0; kx < 7; kx++)
                wb[r & 1][kx] = *(const uint64_t*)&wsh2[r * 7 + kx];
        }
        // dy=0: out row lr0, ky=r (r<=6)
        if (r <= 6) {
            #pragma unroll
            for (int kx = 0; kx < 7; kx++) {
                fma2(acc0a, p[kx],     wb[r & 1][kx]);
                fma2(acc0b, p[kx + 2], wb[r & 1][kx]);
            }
        }
        // dy=1: out row lr0+1, ky=r-1 (r>=1)
        if (r >= 1) {
            #pragma unroll
            for (int kx = 0; kx < 7; kx++) {
                fma2(acc1a, p[kx],     wb[(r - 1) & 1][kx]);
                fma2(acc1b, p[kx + 2], wb[(r - 1) & 1][kx]);
            }
        }
    }

    // epilogue: fp16 pack + store (8B per row, coalesced across tc)
    float f0, f1, f2, f3;
    uint32_t base = (uint32_t)bc * 4096u + (uint32_t)(rowBase + lr0) * 64u + (uint32_t)c0;

    unpack2(f0, f1, acc0a); unpack2(f2, f3, acc0b);
    {
        __half2 ha, hb;
        ha.x = __float2half_rn(f0); ha.y = __float2half_rn(f1);
        hb.x = __float2half_rn(f2); hb.y = __float2half_rn(f3);
        uint2 st; st.x = *(uint32_t*)&ha; st.y = *(uint32_t*)&hb;
        *(uint2*)&g_bh[base] = st;
    }
    unpack2(f0, f1, acc1a); unpack2(f2, f3, acc1b);
    {
        __half2 ha, hb;
        ha.x = __float2half_rn(f0); ha.y = __float2half_rn(f1);
        hb.x = __float2half_rn(f2); hb.y = __float2half_rn(f3);
        uint2 st; st.x = *(uint32_t*)&ha; st.y = *(uint32_t*)&hb;
        *(uint2*)&g_bh[base + 64] = st;
    }
}

// ---------------------------------------------------------------------------
// Kernel 5: pointwise GEMM via mma.sync fp16 single pass, 3-stage cp.async.
//   Stage (18432 B): A[128x80B] @0, B[32x256B] @10240.
// ---------------------------------------------------------------------------
__global__ void __launch_bounds__(256) pw_gemm_mma(float* __restrict__ out) {
    extern __shared__ __align__(128) char sm[];
    const uint32_t smb = smem_u32(sm);
    const uint32_t STAGE = 18432;

    const int tid = threadIdx.x;
    const int wid = tid >> 5, lane = tid & 31;
    const int warp_m = wid & 1;
    const int warp_n = wid >> 1;
    const int n0 = blockIdx.x * 128;
    const int m0 = blockIdx.y * 128;
    const int b  = blockIdx.z;

    float acc[4][4][4];
    #pragma unroll
    for (int i = 0; i < 4; i++)
        #pragma unroll
        for (int j = 0; j < 4; j++)
            #pragma unroll
            for (int q = 0; q < 4; q++) acc[i][j][q] = 0.f;

    const int lm16 = lane & 15, lhi = lane >> 4;
    const uint32_t aRowOff = (uint32_t)(warp_m * 64 + lm16) * 80 + (uint32_t)lhi * 16;
    const int bN = warp_n * 32 + lhi * 8;

    float* ob = out + (size_t)b * 1048576;

    auto issue = [&](int kc, uint32_t sbase) {
        #pragma unroll
        for (int i = 0; i < 2; i++) {
            int lin = tid + i * 256;
            int r = lin >> 2, j = lin & 3;
            const __half* src = g_pwh + (size_t)(m0 + r) * 256 + kc * 32 + j * 8;
            cp16(sbase + r * 80 + j * 16, src);
        }
        #pragma unroll
        for (int i = 0; i < 2; i++) {
            int lin = tid + i * 256;
            int k = lin >> 4, j16 = lin & 15;
            const __half* src = g_bh + (size_t)b * 1048576
                + (size_t)(kc * 32 + k) * 4096 + n0 + j16 * 8;
            cp16(sbase + 10240 + (uint32_t)k * 256
                 + (uint32_t)((j16 ^ (k & 7)) * 16), src);
        }
        cp_commit();
    };

    issue(0, smb);
    issue(1, smb + STAGE);

    for (int kc = 0; kc < 8; kc++) {
        const uint32_t sbase = smb + (uint32_t)(kc % 3) * STAGE;
        if (kc == 7) cp_wait0(); else cp_wait1();
        __syncthreads();
        if (kc < 6) issue(kc + 2, smb + (uint32_t)((kc + 2) % 3) * STAGE);

        const uint32_t aB = sbase, bB = sbase + 10240;
        #pragma unroll
        for (int ks = 0; ks < 2; ks++) {
            uint32_t bf[2][4];
            #pragma unroll
            for (int p = 0; p < 2; p++) {
                int k = ks * 16 + lm16;
                int n = bN + p * 16;
                uint32_t off = (uint32_t)k * 256
                             + (uint32_t)(((n >> 3) ^ (k & 7)) * 16);
                ldsm_x4_t(bf[p], bB + off);
            }
            uint32_t af[4][4];
            #pragma unroll
            for (int mi = 0; mi < 4; mi++)
                ldsm_x4(af[mi], aB + aRowOff + (uint32_t)mi * (16 * 80)
                               + (uint32_t)ks * 32);
            #pragma unroll
            for (int mi = 0; mi < 4; mi++) {
                #pragma unroll
                for (int p = 0; p < 2; p++) {
                    mma_f16(acc[mi][2 * p],     af[mi], &bf[p][0]);
                    mma_f16(acc[mi][2 * p + 1], af[mi], &bf[p][2]);
                }
            }
        }
    }

    const int rowBase = m0 + warp_m * 64 + (lane >> 2);
    const int colBase = n0 + warp_n * 32 + (lane & 3) * 2;
    #pragma unroll
    for (int mi = 0; mi < 4; mi++) {
        #pragma unroll
        for (int ni = 0; ni < 4; ni++) {
            int r = rowBase + mi * 16;
            int c = colBase + ni * 8;
            *(float2*)&ob[(size_t)r * 4096 + c] =
                make_float2(acc[mi][ni][0], acc[mi][ni][1]);
            *(float2*)&ob[(size_t)(r + 8) * 4096 + c] =
                make_float2(acc[mi][ni][2], acc[mi][ni][3]);
        }
    }
}

// ---------------------------------------------------------------------------
// launch
// ---------------------------------------------------------------------------
extern "C" void kernel_launch(void* const* d_in, const int* in_sizes, int n_in,
                              void* d_out, int out_size) {
    const float* x   = (const float*)d_in[0];  // [16,256,64,64]
    const float* dw  = (const float*)d_in[1];  // [256,1,7,7]
    const float* pwm = (const float*)d_in[2];  // [256,256]
    const float* w1  = (const float*)d_in[3];  // [64,256]
    const float* b1  = (const float*)d_in[4];  // [64]
    const float* w2  = (const float*)d_in[5];  // [12544,64]
    const float* b2  = (const float*)d_in[6];  // [12544]
    float* out = (float*)d_out;                // [16,256,64,64] fp32

    cudaFuncSetAttribute(pw_gemm_mma, cudaFuncAttributeMaxDynamicSharedMemorySize, 55296);

    pw_split<<<256, 256>>>(pwm);
    pool_kernel<<<4096, 256>>>(x);
    mlp1_kernel<<<16, 64>>>(w1, b1);
    fuse_kernel<<<dim3(98, 2), 256>>>(dw, w2, b2);
    dw_kernel<<<dim3(2, 4096), 256>>>(x);
    pw_gemm_mma<<<dim3(32, 2, 16), 256, 55296>>>(out);
}

// round 11
// speedup vs baseline: 1.1422x; 1.1422x over previous
#include <cuda_runtime.h>
#include <cuda_fp16.h>
#include <math.h>
#include <stdint.h>

#define DINLINE __device__ __forceinline__

// Problem constants: B=16, C=256, H=W=64, K=7, C/4=64, C*K*K=12544

// ---- scratch (static device allocations: allowed) ----
__device__ __align__(128) float g_pooled[16 * 256];            // [B, C]
__device__ __align__(128) float g_h[16 * 64];                  // [B, C/4]
__device__ __align__(128) float g_fused[16 * 256 * 49];        // [B, C, 49]
__device__ __align__(128) __half g_bh[16u*256u*64u*64u];       // dw out, fp16 (32 MB)
__device__ __align__(128) __half g_pwh[256 * 256];             // fp16 pw weights

// ===========================================================================
// PTX helpers (all legal on plain sm_100 target)
// ===========================================================================
DINLINE uint32_t smem_u32(const void* p) {
    uint32_t a;
    asm("{ .reg .u64 t; cvta.to.shared.u64 t, %1; cvt.u32.u64 %0, t; }" : "=r"(a) : "l"(p));
    return a;
}
DINLINE void ldsm_x4(uint32_t* r, uint32_t addr) {
    asm volatile("ldmatrix.sync.aligned.m8n8.x4.shared.b16 {%0,%1,%2,%3}, [%4];"
                 : "=r"(r[0]), "=r"(r[1]), "=r"(r[2]), "=r"(r[3]) : "r"(addr));
}
DINLINE void ldsm_x4_t(uint32_t* r, uint32_t addr) {
    asm volatile("ldmatrix.sync.aligned.m8n8.x4.trans.shared.b16 {%0,%1,%2,%3}, [%4];"
                 : "=r"(r[0]), "=r"(r[1]), "=r"(r[2]), "=r"(r[3]) : "r"(addr));
}
DINLINE void mma_f16(float* d, const uint32_t* a, const uint32_t* b) {
    asm volatile(
        "mma.sync.aligned.m16n8k16.row.col.f32.f16.f16.f32 "
        "{%0,%1,%2,%3}, {%4,%5,%6,%7}, {%8,%9}, {%0,%1,%2,%3};"
        : "+f"(d[0]), "+f"(d[1]), "+f"(d[2]), "+f"(d[3])
        : "r"(a[0]), "r"(a[1]), "r"(a[2]), "r"(a[3]), "r"(b[0]), "r"(b[1]));
}
DINLINE void cp16(uint32_t dst, const void* src) {
    asm volatile("cp.async.cg.shared.global [%0], [%1], 16;"
                 :: "r"(dst), "l"(__cvta_generic_to_global(src)));
}
DINLINE void cp_commit() { asm volatile("cp.async.commit_group;" ::: "memory"); }
DINLINE void cp_wait0()  { asm volatile("cp.async.wait_group 0;" ::: "memory"); }
DINLINE void cp_wait1()  { asm volatile("cp.async.wait_group 1;" ::: "memory"); }

// ---------------------------------------------------------------------------
// Kernel 0: pw weights -> fp16
// ---------------------------------------------------------------------------
__global__ void pw_split(const float* __restrict__ pw) {
    int i = blockIdx.x * 256 + threadIdx.x;   // 65536 elems
    g_pwh[i] = __float2half_rn(pw[i]);
}

// ---------------------------------------------------------------------------
// Kernel 1: global average pool
// ---------------------------------------------------------------------------
__global__ void pool_kernel(const float* __restrict__ x) {
    int bc = blockIdx.x;
    const float4* xp = (const float4*)(x + (size_t)bc * 4096);
    float s = 0.f;
    #pragma unroll 4
    for (int i = threadIdx.x; i < 1024; i += 256) {
        float4 v = xp[i];
        s += (v.x + v.y) + (v.z + v.w);
    }
    __shared__ float red[256];
    red[threadIdx.x] = s;
    __syncthreads();
    for (int off = 128; off > 0; off >>= 1) {
        if (threadIdx.x < off) red[threadIdx.x] += red[threadIdx.x + off];
        __syncthreads();
    }
    if (threadIdx.x == 0) g_pooled[bc] = red[0] * (1.f / 4096.f);
}

// ---------------------------------------------------------------------------
// Kernel 2: h = gelu(pooled @ w1^T + b1)
// ---------------------------------------------------------------------------
__global__ void mlp1_kernel(const float* __restrict__ w1, const float* __restrict__ b1) {
    int b = blockIdx.x;
    int j = threadIdx.x;   // 0..63
    __shared__ float p[256];
    for (int i = threadIdx.x; i < 256; i += 64) p[i] = g_pooled[b * 256 + i];
    __syncthreads();
    float s = b1[j];
    const float* wr = w1 + (size_t)j * 256;
    #pragma unroll 8
    for (int c = 0; c < 256; c++) s += p[c] * wr[c];
    g_h[b * 64 + j] = 0.5f * s * (1.0f + erff(s * 0.70710678118654752f));
}

// ---------------------------------------------------------------------------
// Kernel 3: fused[b,wi] = dw[wi] + b2[wi] + sum_j h[b,j]*w2[wi,j]
// grid (98 wi-tiles, 2 b-groups); thread: 1 wi x 4 b.
// ---------------------------------------------------------------------------
__global__ void __launch_bounds__(256) fuse_kernel(const float* __restrict__ dw,
                                                   const float* __restrict__ w2,
                                                   const float* __restrict__ b2) {
    __shared__ float hs[8 * 64];
    __shared__ float w2s[128 * 68];
    int tid = threadIdx.x;
    int wi0 = blockIdx.x * 128;
    int b0 = blockIdx.y * 8;

    if (tid < 128) *(float4*)(hs + tid * 4) = *(const float4*)(g_h + b0 * 64 + tid * 4);
    #pragma unroll
    for (int i = 0; i < 8; i++) {
        int lin = tid + i * 256;
        int r = lin >> 4, j4 = lin & 15;
        float4 v = *(const float4*)(w2 + (size_t)(wi0 + r) * 64 + j4 * 4);
        *(float4*)(w2s + r * 68 + j4 * 4) = v;
    }
    __syncthreads();

    int wiL = tid & 127;
    int bg = (tid >> 7) * 4;
    int wi = wi0 + wiL;
    float base = dw[wi] + b2[wi];
    float acc[4];
    #pragma unroll
    for (int bb = 0; bb < 4; bb++) acc[bb] = base;

    const float* wr = w2s + wiL * 68;
    #pragma unroll
    for (int j4 = 0; j4 < 16; j4++) {
        float4 w = *(const float4*)(wr + j4 * 4);
        #pragma unroll
        for (int bb = 0; bb < 4; bb++) {
            float4 h = *(const float4*)(hs + (bg + bb) * 64 + j4 * 4);
            acc[bb] += w.x * h.x + w.y * h.y + w.z * h.z + w.w * h.w;
        }
    }
    #pragma unroll
    for (int bb = 0; bb < 4; bb++)
        g_fused[(size_t)(b0 + bg + bb) * 12544 + wi] = acc[bb];
}

// ---------------------------------------------------------------------------
// Kernel 4: per-sample depthwise 7x7 conv, pad=3.  SCALAR FFMA (f32x2 reverted).
// Block = 32-row tile; thread = 2 rows x 4 cols (8 outputs).
// v[0..9] loaded once per input row, reused across 4 columns.
// ---------------------------------------------------------------------------
__global__ void __launch_bounds__(256, 2) dw_kernel(const float* __restrict__ x) {
    int bc = blockIdx.y;
    int rowBase = blockIdx.x * 32;
    const float* xp = x + (size_t)bc * 4096;

    __shared__ __align__(16) float s[38 * 70];
    __shared__ float wsh[49];

    if (threadIdx.x < 49) wsh[threadIdx.x] = g_fused[bc * 49 + threadIdx.x];

    for (int i = threadIdx.x; i < 38 * 70; i += 256) {
        int r = i / 70, cc = i - r * 70;
        int gr = rowBase + r - 3, gc = cc - 3;
        s[i] = (gr >= 0 && gr < 64 && gc >= 0 && gc < 64) ? xp[gr * 64 + gc] : 0.f;
    }
    __syncthreads();

    float w[49];
    #pragma unroll
    for (int q = 0; q < 49; q++) w[q] = wsh[q];
    #pragma unroll
    for (int q = 0; q < 49; q++) asm volatile("" : "+f"(w[q]));

    const int c0  = (threadIdx.x & 15) * 4;   // output cols c0..c0+3
    const int lr0 = (threadIdx.x >> 4) * 2;   // local output rows lr0, lr0+1

    float acc0[4] = {0.f, 0.f, 0.f, 0.f};
    float acc1[4] = {0.f, 0.f, 0.f, 0.f};

    #pragma unroll
    for (int r = 0; r < 8; r++) {             // smem rows lr0+r
        float v[10];
        const float* row = s + (lr0 + r) * 70 + c0;
        #pragma unroll
        for (int q = 0; q < 5; q++) *(float2*)&v[q * 2] = *(const float2*)(row + q * 2);

        if (r <= 6) {                         // out row lr0, ky=r
            #pragma unroll
            for (int kx = 0; kx < 7; kx++) {
                float wv = w[r * 7 + kx];
                #pragma unroll
                for (int c = 0; c < 4; c++) acc0[c] += v[kx + c] * wv;
            }
        }
        if (r >= 1) {                         // out row lr0+1, ky=r-1
            #pragma unroll
            for (int kx = 0; kx < 7; kx++) {
                float wv = w[(r - 1) * 7 + kx];
                #pragma unroll
                for (int c = 0; c < 4; c++) acc1[c] += v[kx + c] * wv;
            }
        }
    }

    // epilogue: fp16 pack + uint2 store per row (8B, coalesced across threads)
    uint32_t base = (uint32_t)bc * 4096u + (uint32_t)(rowBase + lr0) * 64u + (uint32_t)c0;
    {
        __half2 ha, hb;
        ha.x = __float2half_rn(acc0[0]); ha.y = __float2half_rn(acc0[1]);
        hb.x = __float2half_rn(acc0[2]); hb.y = __float2half_rn(acc0[3]);
        uint2 st; st.x = *(uint32_t*)&ha; st.y = *(uint32_t*)&hb;
        *(uint2*)&g_bh[base] = st;
    }
    {
        __half2 ha, hb;
        ha.x = __float2half_rn(acc1[0]); ha.y = __float2half_rn(acc1[1]);
        hb.x = __float2half_rn(acc1[2]); hb.y = __float2half_rn(acc1[3]);
        uint2 st; st.x = *(uint32_t*)&ha; st.y = *(uint32_t*)&hb;
        *(uint2*)&g_bh[base + 64] = st;
    }
}

// ---------------------------------------------------------------------------
// Kernel 5: pointwise GEMM via mma.sync fp16 single pass, 3-stage cp.async.
//   Stage (18432 B): A[128x80B] @0, B[32x256B] @10240.   (unchanged from R9)
// ---------------------------------------------------------------------------
__global__ void __launch_bounds__(256) pw_gemm_mma(float* __restrict__ out) {
    extern __shared__ __align__(128) char sm[];
    const uint32_t smb = smem_u32(sm);
    const uint32_t STAGE = 18432;

    const int tid = threadIdx.x;
    const int wid = tid >> 5, lane = tid & 31;
    const int warp_m = wid & 1;
    const int warp_n = wid >> 1;
    const int n0 = blockIdx.x * 128;
    const int m0 = blockIdx.y * 128;
    const int b  = blockIdx.z;

    float acc[4][4][4];
    #pragma unroll
    for (int i = 0; i < 4; i++)
        #pragma unroll
        for (int j = 0; j < 4; j++)
            #pragma unroll
            for (int q = 0; q < 4; q++) acc[i][j][q] = 0.f;

    const int lm16 = lane & 15, lhi = lane >> 4;
    const uint32_t aRowOff = (uint32_t)(warp_m * 64 + lm16) * 80 + (uint32_t)lhi * 16;
    const int bN = warp_n * 32 + lhi * 8;

    float* ob = out + (size_t)b * 1048576;

    auto issue = [&](int kc, uint32_t sbase) {
        #pragma unroll
        for (int i = 0; i < 2; i++) {
            int lin = tid + i * 256;
            int r = lin >> 2, j = lin & 3;
            const __half* src = g_pwh + (size_t)(m0 + r) * 256 + kc * 32 + j * 8;
            cp16(sbase + r * 80 + j * 16, src);
        }
        #pragma unroll
        for (int i = 0; i < 2; i++) {
            int lin = tid + i * 256;
            int k = lin >> 4, j16 = lin & 15;
            const __half* src = g_bh + (size_t)b * 1048576
                + (size_t)(kc * 32 + k) * 4096 + n0 + j16 * 8;
            cp16(sbase + 10240 + (uint32_t)k * 256
                 + (uint32_t)((j16 ^ (k & 7)) * 16), src);
        }
        cp_commit();
    };

    issue(0, smb);
    issue(1, smb + STAGE);

    for (int kc = 0; kc < 8; kc++) {
        const uint32_t sbase = smb + (uint32_t)(kc % 3) * STAGE;
        if (kc == 7) cp_wait0(); else cp_wait1();
        __syncthreads();
        if (kc < 6) issue(kc + 2, smb + (uint32_t)((kc + 2) % 3) * STAGE);

        const uint32_t aB = sbase, bB = sbase + 10240;
        #pragma unroll
        for (int ks = 0; ks < 2; ks++) {
            uint32_t bf[2][4];
            #pragma unroll
            for (int p = 0; p < 2; p++) {
                int k = ks * 16 + lm16;
                int n = bN + p * 16;
                uint32_t off = (uint32_t)k * 256
                             + (uint32_t)(((n >> 3) ^ (k & 7)) * 16);
                ldsm_x4_t(bf[p], bB + off);
            }
            uint32_t af[4][4];
            #pragma unroll
            for (int mi = 0; mi < 4; mi++)
                ldsm_x4(af[mi], aB + aRowOff + (uint32_t)mi * (16 * 80)
                               + (uint32_t)ks * 32);
            #pragma unroll
            for (int mi = 0; mi < 4; mi++) {
                #pragma unroll
                for (int p = 0; p < 2; p++) {
                    mma_f16(acc[mi][2 * p],     af[mi], &bf[p][0]);
                    mma_f16(acc[mi][2 * p + 1], af[mi], &bf[p][2]);
                }
            }
        }
    }

    const int rowBase = m0 + warp_m * 64 + (lane >> 2);
    const int colBase = n0 + warp_n * 32 + (lane & 3) * 2;
    #pragma unroll
    for (int mi = 0; mi < 4; mi++) {
        #pragma unroll
        for (int ni = 0; ni < 4; ni++) {
            int r = rowBase + mi * 16;
            int c = colBase + ni * 8;
            *(float2*)&ob[(size_t)r * 4096 + c] =
                make_float2(acc[mi][ni][0], acc[mi][ni][1]);
            *(float2*)&ob[(size_t)(r + 8) * 4096 + c] =
                make_float2(acc[mi][ni][2], acc[mi][ni][3]);
        }
    }
}

// ---------------------------------------------------------------------------
// launch
// ---------------------------------------------------------------------------
extern "C" void kernel_launch(void* const* d_in, const int* in_sizes, int n_in,
                              void* d_out, int out_size) {
    const float* x   = (const float*)d_in[0];  // [16,256,64,64]
    const float* dw  = (const float*)d_in[1];  // [256,1,7,7]
    const float* pwm = (const float*)d_in[2];  // [256,256]
    const float* w1  = (const float*)d_in[3];  // [64,256]
    const float* b1  = (const float*)d_in[4];  // [64]
    const float* w2  = (const float*)d_in[5];  // [12544,64]
    const float* b2  = (const float*)d_in[6];  // [12544]
    float* out = (float*)d_out;                // [16,256,64,64] fp32

    cudaFuncSetAttribute(pw_gemm_mma, cudaFuncAttributeMaxDynamicSharedMemorySize, 55296);

    pw_split<<<256, 256>>>(pwm);
    pool_kernel<<<4096, 256>>>(x);
    mlp1_kernel<<<16, 64>>>(w1, b1);
    fuse_kernel<<<dim3(98, 2), 256>>>(dw, w2, b2);
    dw_kernel<<<dim3(2, 4096), 256>>>(x);
    pw_gemm_mma<<<dim3(32, 2, 16), 256, 55296>>>(out);
}